// round 9
// baseline (speedup 1.0000x reference)
#include <cuda_runtime.h>
#include <cuda_fp16.h>
#include <math.h>

#define NN 10000
#define NE 200000
#define NT 400000
#define NORB 9
#define HD 128
#define CFD 64
#define CD 32
#define R_TOT (NE * NORB)   // 1,800,000 flattened (edge,orb) rows

typedef unsigned long long u64;
typedef unsigned int u32;

// ---------------- scratch (device globals; no allocation allowed) ----------
__device__ float g_h[NN * 64];                     // [0:32)=silu(xh), [32:64)=sigm(xk)
__device__ __half g_cji_c[(size_t)NE * NORB * CD]; // 115.2 MB (fp16)
__device__ __half g_ckj_n[(size_t)NE * NORB * CD]; // 115.2 MB (fp16, pre-normalized)
__device__ float g_rbw[NE * NORB];
__device__ float g_agg[(size_t)NE * CD];
__device__ float g_nf[(size_t)NE * CD];            // node-feature MLP output
__device__ float g_acc[NN * CD];

// ---- fast transcendentals: 1 MUFU instead of 2 ------------------------------
__device__ __forceinline__ float tanh_f(float x) {
    float r; asm("tanh.approx.f32 %0,%1;" : "=f"(r) : "f"(x)); return r;
}
__device__ __forceinline__ float sigm(float x) {
    return fmaf(tanh_f(0.5f * x), 0.5f, 0.5f);
}
__device__ __forceinline__ float silu(float x) {
    return x * sigm(x);
}

__device__ __forceinline__ float warp_sum(float s) {
#pragma unroll
    for (int off = 16; off; off >>= 1) s += __shfl_xor_sync(0xffffffffu, s, off);
    return s;
}

// ---- packed fp32x2 FFMA2 (k5b W4 gemm) -------------------------------------
__device__ __forceinline__ void fma2(u64& d, u64 a, u64 b) {
    asm("fma.rn.f32x2 %0,%1,%2,%0;" : "+l"(d) : "l"(a), "l"(b));
}
__device__ __forceinline__ float unp_sum(u64 v) {
    float x, y; asm("mov.b64 {%0,%1},%2;" : "=f"(x), "=f"(y) : "l"(v)); return x + y;
}

// ---- tf32 helpers -----------------------------------------------------------
__device__ __forceinline__ u32 to_tf32(float f) {
    u32 r; asm("cvt.rna.tf32.f32 %0,%1;" : "=r"(r) : "f"(f)); return r;
}
__device__ __forceinline__ void mma_tf32(float& c0, float& c1, float& c2, float& c3,
                                         u32 a0, u32 a1, u32 a2, u32 a3,
                                         u32 b0, u32 b1) {
    asm("mma.sync.aligned.m16n8k8.row.col.f32.tf32.tf32.f32 "
        "{%0,%1,%2,%3},{%4,%5,%6,%7},{%8,%9},{%0,%1,%2,%3};"
        : "+f"(c0), "+f"(c1), "+f"(c2), "+f"(c3)
        : "r"(a0), "r"(a1), "r"(a2), "r"(a3), "r"(b0), "r"(b1));
}

// ---------------- K0: zero accumulators + rb_w = rb * cutoff_w -------------
__global__ void k0_init(const float* __restrict__ rb, const float* __restrict__ cw) {
    int i = blockIdx.x * blockDim.x + threadIdx.x;
    if (i < NE * CD) g_agg[i] = 0.f;
    if (i < NN * CD) g_acc[i] = 0.f;
    if (i < NE * NORB) g_rbw[i] = rb[i] * cw[i / NORB];
}

// ---------------- K1: h = x @ W1^T + b1; store silu(xh) / sigm(xk) ----------
__global__ void __launch_bounds__(256) k1_node(const float* __restrict__ x,
                                               const float* __restrict__ W1,
                                               const float* __restrict__ b1) {
    __shared__ float sW[HD * 64];
    __shared__ float sx[4][HD];
    int tid = threadIdx.x;
    for (int idx = tid; idx < 64 * HD; idx += 256) {
        int o = idx / HD, k = idx % HD;
        sW[k * 64 + o] = W1[idx];
    }
    int n0 = blockIdx.x * 4;
#pragma unroll
    for (int r = 0; r < 4; r++) {
        int n = n0 + r;
        if (n < NN)
            for (int k = tid; k < HD; k += 256) sx[r][k] = x[n * HD + k];
    }
    __syncthreads();
    int r = tid / 64, o = tid % 64;
    int n = n0 + r;
    if (n >= NN) return;
    float acc = b1[o];
#pragma unroll 8
    for (int k = 0; k < HD; k++) acc = fmaf(sx[r][k], sW[k * 64 + o], acc);
    g_h[n * 64 + o] = (o < 32) ? silu(acc) : sigm(acc);
}

// ---------------- K2: edge coeff MLP, tf32 tensor cores, A2 aliased on A1 ----
__global__ void __launch_bounds__(256) k2_mma(const float* __restrict__ cji,
                                              const float* __restrict__ W2,
                                              const float* __restrict__ W3) {
    __shared__ u32 sW2[32 * 68];       // [n][k] pad 68 (tf32 bits)
    __shared__ u32 sW3[64 * 36];       // [n][k] pad 36
    __shared__ u32 sA1[8][16 * 68];    // per-warp tile; A2 overlays same buffer
    int tid = threadIdx.x;
    for (int idx = tid; idx < 32 * 64; idx += 256) {
        int n = idx >> 6, k = idx & 63;
        sW2[n * 68 + k] = to_tf32(W2[idx]);
    }
    for (int idx = tid; idx < 64 * 32; idx += 256) {
        int n = idx >> 5, k = idx & 31;
        sW3[n * 36 + k] = to_tf32(W3[idx]);
    }
    __syncthreads();

    int w = tid >> 5, lane = tid & 31;
    int gq = lane >> 2, tq = lane & 3;
    long row0 = (long)blockIdx.x * 128 + w * 16;
    u32* A1 = sA1[w];
    u32* A2 = sA1[w];   // alias: A1 fully consumed into regs before A2 writes

    for (int i = lane; i < 256; i += 32) {
        int rl = i >> 4, c4 = i & 15;
        long rg = row0 + rl;
        uint4 v = make_uint4(0u, 0u, 0u, 0u);
        if (rg < R_TOT) {
            float4 f = *(const float4*)(cji + rg * 64 + c4 * 4);
            v.x = to_tf32(silu(f.x)); v.y = to_tf32(silu(f.y));
            v.z = to_tf32(silu(f.z)); v.w = to_tf32(silu(f.w));
        }
        *(uint4*)&A1[rl * 68 + c4 * 4] = v;
    }
    __syncwarp();

    float c1[4][4];
#pragma unroll
    for (int nt = 0; nt < 4; nt++)
#pragma unroll
        for (int j = 0; j < 4; j++) c1[nt][j] = 0.f;
#pragma unroll
    for (int k0 = 0; k0 < 64; k0 += 8) {
        u32 a0 = A1[gq * 68 + k0 + tq];
        u32 a1 = A1[(gq + 8) * 68 + k0 + tq];
        u32 a2 = A1[gq * 68 + k0 + tq + 4];
        u32 a3 = A1[(gq + 8) * 68 + k0 + tq + 4];
#pragma unroll
        for (int nt = 0; nt < 4; nt++) {
            u32 b0 = sW2[(nt * 8 + gq) * 68 + k0 + tq];
            u32 b1 = sW2[(nt * 8 + gq) * 68 + k0 + tq + 4];
            mma_tf32(c1[nt][0], c1[nt][1], c1[nt][2], c1[nt][3], a0, a1, a2, a3, b0, b1);
        }
    }
    __syncwarp();
#pragma unroll
    for (int nt = 0; nt < 4; nt++) {
        A2[gq * 36 + nt * 8 + 2 * tq]           = to_tf32(silu(c1[nt][0]));
        A2[gq * 36 + nt * 8 + 2 * tq + 1]       = to_tf32(silu(c1[nt][1]));
        A2[(gq + 8) * 36 + nt * 8 + 2 * tq]     = to_tf32(silu(c1[nt][2]));
        A2[(gq + 8) * 36 + nt * 8 + 2 * tq + 1] = to_tf32(silu(c1[nt][3]));
    }
    __syncwarp();

    float c2[8][4];
#pragma unroll
    for (int nt = 0; nt < 8; nt++)
#pragma unroll
        for (int j = 0; j < 4; j++) c2[nt][j] = 0.f;
#pragma unroll
    for (int k0 = 0; k0 < 32; k0 += 8) {
        u32 a0 = A2[gq * 36 + k0 + tq];
        u32 a1 = A2[(gq + 8) * 36 + k0 + tq];
        u32 a2 = A2[gq * 36 + k0 + tq + 4];
        u32 a3 = A2[(gq + 8) * 36 + k0 + tq + 4];
#pragma unroll
        for (int nt = 0; nt < 8; nt++) {
            u32 b0 = sW3[(nt * 8 + gq) * 36 + k0 + tq];
            u32 b1 = sW3[(nt * 8 + gq) * 36 + k0 + tq + 4];
            mma_tf32(c2[nt][0], c2[nt][1], c2[nt][2], c2[nt][3], a0, a1, a2, a3, b0, b1);
        }
    }

    long rA = row0 + gq, rB = row0 + gq + 8;
    if (rA < R_TOT) {
#pragma unroll
        for (int nt = 0; nt < 4; nt++)
            *(__half2*)&g_cji_c[rA * 32 + nt * 8 + 2 * tq] = __floats2half2_rn(c2[nt][0], c2[nt][1]);
    }
    if (rB < R_TOT) {
#pragma unroll
        for (int nt = 0; nt < 4; nt++)
            *(__half2*)&g_cji_c[rB * 32 + nt * 8 + 2 * tq] = __floats2half2_rn(c2[nt][2], c2[nt][3]);
    }
    float sa = 0.f, sb = 0.f;
#pragma unroll
    for (int nt = 4; nt < 8; nt++) {
        sa = fmaf(c2[nt][0], c2[nt][0], fmaf(c2[nt][1], c2[nt][1], sa));
        sb = fmaf(c2[nt][2], c2[nt][2], fmaf(c2[nt][3], c2[nt][3], sb));
    }
    sa += __shfl_xor_sync(0xffffffffu, sa, 1);
    sa += __shfl_xor_sync(0xffffffffu, sa, 2);
    sb += __shfl_xor_sync(0xffffffffu, sb, 1);
    sb += __shfl_xor_sync(0xffffffffu, sb, 2);
    float ia = 1.f / fmaxf(sqrtf(sa), 1e-12f);
    float ib = 1.f / fmaxf(sqrtf(sb), 1e-12f);
    if (rA < R_TOT) {
#pragma unroll
        for (int nt = 4; nt < 8; nt++)
            *(__half2*)&g_ckj_n[rA * 32 + (nt - 4) * 8 + 2 * tq] =
                __floats2half2_rn(c2[nt][0] * ia, c2[nt][1] * ia);
    }
    if (rB < R_TOT) {
#pragma unroll
        for (int nt = 4; nt < 8; nt++)
            *(__half2*)&g_ckj_n[rB * 32 + (nt - 4) * 8 + 2 * tq] =
                __floats2half2_rn(c2[nt][2] * ib, c2[nt][3] * ib);
    }
}

// ---------------- K5a: nf MLP on tensor cores, A2 aliased on A1 --------------
__global__ void __launch_bounds__(256) k5a_nf(const float* __restrict__ W5,
                                              const float* __restrict__ b5,
                                              const float* __restrict__ W6,
                                              const float* __restrict__ b6,
                                              const int* __restrict__ idx_i,
                                              const int* __restrict__ idx_j) {
    __shared__ u32 sW5[32 * 68];
    __shared__ u32 sW6[32 * 36];
    __shared__ float sb5[32], sb6[32];
    __shared__ u32 sA1[8][16 * 68];   // A2 overlays
    int tid = threadIdx.x;
    for (int idx = tid; idx < 32 * 64; idx += 256) {
        int n = idx >> 6, k = idx & 63;
        sW5[n * 68 + k] = to_tf32(W5[idx]);
    }
    for (int idx = tid; idx < 32 * 32; idx += 256) {
        int n = idx >> 5, k = idx & 31;
        sW6[n * 36 + k] = to_tf32(W6[idx]);
    }
    if (tid < 32) { sb5[tid] = b5[tid]; sb6[tid] = b6[tid]; }
    __syncthreads();

    int w = tid >> 5, lane = tid & 31;
    int gq = lane >> 2, tq = lane & 3;
    long row0 = (long)blockIdx.x * 128 + w * 16;
    u32* A1 = sA1[w];
    u32* A2 = sA1[w];

    for (int i = lane; i < 256; i += 32) {
        int rl = i >> 4, c4 = i & 15;
        long e = row0 + rl;
        uint4 v = make_uint4(0u, 0u, 0u, 0u);
        if (e < NE) {
            int n = (c4 < 8) ? __ldg(&idx_i[e]) : __ldg(&idx_j[e]);
            float4 f = *(const float4*)&g_h[n * 64 + (c4 & 7) * 4];
            v.x = to_tf32(f.x); v.y = to_tf32(f.y);
            v.z = to_tf32(f.z); v.w = to_tf32(f.w);
        }
        *(uint4*)&A1[rl * 68 + c4 * 4] = v;
    }
    __syncwarp();

    float c1[4][4];
#pragma unroll
    for (int nt = 0; nt < 4; nt++)
#pragma unroll
        for (int j = 0; j < 4; j++) c1[nt][j] = 0.f;
#pragma unroll
    for (int k0 = 0; k0 < 64; k0 += 8) {
        u32 a0 = A1[gq * 68 + k0 + tq];
        u32 a1 = A1[(gq + 8) * 68 + k0 + tq];
        u32 a2 = A1[gq * 68 + k0 + tq + 4];
        u32 a3 = A1[(gq + 8) * 68 + k0 + tq + 4];
#pragma unroll
        for (int nt = 0; nt < 4; nt++) {
            u32 b0 = sW5[(nt * 8 + gq) * 68 + k0 + tq];
            u32 b1 = sW5[(nt * 8 + gq) * 68 + k0 + tq + 4];
            mma_tf32(c1[nt][0], c1[nt][1], c1[nt][2], c1[nt][3], a0, a1, a2, a3, b0, b1);
        }
    }
    __syncwarp();
#pragma unroll
    for (int nt = 0; nt < 4; nt++) {
        int col = nt * 8 + 2 * tq;
        A2[gq * 36 + col]           = to_tf32(silu(c1[nt][0] + sb5[col]));
        A2[gq * 36 + col + 1]       = to_tf32(silu(c1[nt][1] + sb5[col + 1]));
        A2[(gq + 8) * 36 + col]     = to_tf32(silu(c1[nt][2] + sb5[col]));
        A2[(gq + 8) * 36 + col + 1] = to_tf32(silu(c1[nt][3] + sb5[col + 1]));
    }
    __syncwarp();

    float c2[4][4];
#pragma unroll
    for (int nt = 0; nt < 4; nt++)
#pragma unroll
        for (int j = 0; j < 4; j++) c2[nt][j] = 0.f;
#pragma unroll
    for (int k0 = 0; k0 < 32; k0 += 8) {
        u32 a0 = A2[gq * 36 + k0 + tq];
        u32 a1 = A2[(gq + 8) * 36 + k0 + tq];
        u32 a2 = A2[gq * 36 + k0 + tq + 4];
        u32 a3 = A2[(gq + 8) * 36 + k0 + tq + 4];
#pragma unroll
        for (int nt = 0; nt < 4; nt++) {
            u32 b0 = sW6[(nt * 8 + gq) * 36 + k0 + tq];
            u32 b1 = sW6[(nt * 8 + gq) * 36 + k0 + tq + 4];
            mma_tf32(c2[nt][0], c2[nt][1], c2[nt][2], c2[nt][3], a0, a1, a2, a3, b0, b1);
        }
    }
    long rA = row0 + gq, rB = row0 + gq + 8;
    if (rA < NE) {
#pragma unroll
        for (int nt = 0; nt < 4; nt++) {
            int col = nt * 8 + 2 * tq;
            *(float2*)&g_nf[rA * 32 + col] =
                make_float2(c2[nt][0] + sb6[col], c2[nt][1] + sb6[col + 1]);
        }
    }
    if (rB < NE) {
#pragma unroll
        for (int nt = 0; nt < 4; nt++) {
            int col = nt * 8 + 2 * tq;
            *(float2*)&g_nf[rB * 32 + col] =
                make_float2(c2[nt][2] + sb6[col], c2[nt][3] + sb6[col + 1]);
        }
    }
}

// ---------------- K3: triplets -> edge aggregation (fp16 gather) -------------
__global__ void __launch_bounds__(256) k3_tri(const float* __restrict__ shb,
                                              const int* __restrict__ e_kj,
                                              const int* __restrict__ e_ji,
                                              const int* __restrict__ t_k) {
    int w = threadIdx.x >> 5, lane = threadIdx.x & 31;
    int t = blockIdx.x * 8 + w;
    if (t >= NT) return;
    int kj = e_kj[t], ji = e_ji[t], kn = t_k[t];
    float acc = 0.f;
#pragma unroll
    for (int d = 0; d < NORB; d++) {
        float cf = __ldg(&g_rbw[kj * NORB + d]) * __ldg(&shb[t * NORB + d]);
        float ck = __half2float(__ldg(&g_ckj_n[((size_t)kj * NORB + d) * CD + lane]));
        acc = fmaf(cf, ck, acc);
    }
    float s = warp_sum(acc * acc);
    float inv = 1.f / fmaxf(sqrtf(s), 1e-12f);
    float tw = acc * inv * g_h[kn * 64 + 32 + lane];  // sigm pre-applied in k1
    atomicAdd(&g_agg[(size_t)ji * CD + lane], tw);
}

// ---------------- K5b: tbw + lcao (batched butterflies) + scatter ------------
__global__ void __launch_bounds__(256) k5b_edge(const float* __restrict__ W4,
                                                const float* __restrict__ b4,
                                                const int* __restrict__ idx_i) {
    __shared__ __align__(16) float sW4[32 * 36];
    __shared__ __align__(16) float sag[8][32];
    int tid = threadIdx.x;
    for (int idx = tid; idx < 32 * 32; idx += 256) {
        int c = idx / 32, k = idx % 32;
        sW4[c * 36 + k] = W4[idx];
    }
    __syncthreads();
    int w = tid >> 5, lane = tid & 31;
    int e = blockIdx.x * 8 + w;
    if (e >= NE) return;

    // hoist independent gathers: cji_c rows, nf, rbw start loading NOW,
    // overlapping the agg-dependent W4 GEMM below.
    float vv[NORB];
    size_t base = (size_t)e * (NORB * CD);
#pragma unroll
    for (int d = 0; d < NORB; d++)
        vv[d] = __half2float(__ldg(&g_cji_c[base + d * 32 + lane]));
    float nf = __ldg(&g_nf[(size_t)e * CD + lane]);
    float rw[NORB];
#pragma unroll
    for (int d = 0; d < NORB; d++) rw[d] = __ldg(&g_rbw[e * NORB + d]);

    // tbw = silu(agg) @ W4^T + b4
    sag[w][lane] = silu(g_agg[(size_t)e * CD + lane]);
    __syncwarp();
    u64 t2 = 0ull;
#pragma unroll
    for (int k4 = 0; k4 < 8; k4++) {
        ulonglong2 wv = *(const ulonglong2*)&sW4[lane * 36 + k4 * 4];
        ulonglong2 av = *(const ulonglong2*)&sag[w][k4 * 4];
        fma2(t2, av.x, wv.x);
        fma2(t2, av.y, wv.y);
    }
    float tb = 1.f + b4[lane] + unp_sum(t2);

    // lcao: lc[c] = tb[c] * sum_d (rbw[d]/||cji_c[d,:]*tb||) * cji_c[d][c]
    float ss[NORB];
#pragma unroll
    for (int d = 0; d < NORB; d++) {
        float t = vv[d] * tb;
        ss[d] = t * t;
    }
#pragma unroll
    for (int off = 16; off; off >>= 1) {
#pragma unroll
        for (int d = 0; d < NORB; d++)
            ss[d] += __shfl_xor_sync(0xffffffffu, ss[d], off);
    }
    float lc = 0.f;
#pragma unroll
    for (int d = 0; d < NORB; d++) {
        float inv = 1.f / fmaxf(sqrtf(ss[d]), 1e-12f);
        lc = fmaf(rw[d] * inv, vv[d], lc);
    }
    lc *= tb;
    float s = warp_sum(lc * lc);
    lc *= 1.f / fmaxf(sqrtf(s), 1e-12f);

    int ni = idx_i[e];
    atomicAdd(&g_acc[ni * CD + lane], lc * nf);
}

// ---------------- K6: out = x + acc @ W7^T ----------------------------------
__global__ void __launch_bounds__(256) k6_out(const float* __restrict__ x,
                                              const float* __restrict__ W7,
                                              float* __restrict__ out) {
    __shared__ float sW[32 * 128];
    __shared__ float sa[2][32];
    int tid = threadIdx.x;
    for (int idx = tid; idx < 128 * 32; idx += 256) {
        int hc = idx / 32, c = idx % 32;
        sW[c * 128 + hc] = W7[idx];
    }
    int n0 = blockIdx.x * 2;
    if (tid < 64) {
        int r = tid >> 5, c = tid & 31;
        int n = n0 + r;
        if (n < NN) sa[r][c] = g_acc[n * 32 + c];
    }
    __syncthreads();
    int r = tid >> 7, hc = tid & 127;
    int n = n0 + r;
    if (n >= NN) return;
    float acc = x[n * 128 + hc];
#pragma unroll
    for (int c = 0; c < 32; c++) acc = fmaf(sa[r][c], sW[c * 128 + hc], acc);
    out[n * 128 + hc] = acc;
}

// ---------------- host launcher ---------------------------------------------
extern "C" void kernel_launch(void* const* d_in, const int* in_sizes, int n_in,
                              void* d_out, int out_size) {
    int o_ii, o_ij, o_tk, o_ekj, o_eji;
    int o_W1, o_b1, o_W2, o_W3, o_W4, o_b4, o_W5, o_b5, o_W6, o_b6, o_W7;
    if (in_sizes[5] == NE) { // dict order: idx_i at slot 5
        o_ii = 5; o_ij = 6; o_tk = 7; o_ekj = 8; o_eji = 9;
        o_W1 = 10; o_b1 = 11; o_W2 = 12; o_W3 = 13; o_W4 = 14; o_b4 = 15;
        o_W5 = 16; o_b5 = 17; o_W6 = 18; o_b6 = 19; o_W7 = 20;
    } else {                 // signature order: W1 at slot 5
        o_W1 = 5; o_b1 = 6; o_W2 = 7; o_W3 = 8; o_W4 = 9; o_b4 = 10;
        o_W5 = 11; o_b5 = 12; o_W6 = 13; o_b6 = 14; o_W7 = 15;
        o_ii = 16; o_ij = 17; o_tk = 18; o_ekj = 19; o_eji = 20;
    }
    const float* x   = (const float*)d_in[0];
    const float* cji = (const float*)d_in[1];
    const float* cw  = (const float*)d_in[2];
    const float* rb  = (const float*)d_in[3];
    const float* shb = (const float*)d_in[4];
    const int* ii  = (const int*)d_in[o_ii];
    const int* ij  = (const int*)d_in[o_ij];
    const int* tk  = (const int*)d_in[o_tk];
    const int* ekj = (const int*)d_in[o_ekj];
    const int* eji = (const int*)d_in[o_eji];
    const float* W1 = (const float*)d_in[o_W1];
    const float* b1 = (const float*)d_in[o_b1];
    const float* W2 = (const float*)d_in[o_W2];
    const float* W3 = (const float*)d_in[o_W3];
    const float* W4 = (const float*)d_in[o_W4];
    const float* b4 = (const float*)d_in[o_b4];
    const float* W5 = (const float*)d_in[o_W5];
    const float* b5 = (const float*)d_in[o_b5];
    const float* W6 = (const float*)d_in[o_W6];
    const float* b6 = (const float*)d_in[o_b6];
    const float* W7 = (const float*)d_in[o_W7];
    float* out = (float*)d_out;

    k0_init<<<(NE * CD + 255) / 256, 256>>>(rb, cw);
    k1_node<<<(NN + 3) / 4, 256>>>(x, W1, b1);
    k2_mma<<<(R_TOT + 127) / 128, 256>>>(cji, W2, W3);
    k5a_nf<<<(NE + 127) / 128, 256>>>(W5, b5, W6, b6, ii, ij);
    k3_tri<<<(NT + 7) / 8, 256>>>(shb, ekj, eji, tk);
    k5b_edge<<<(NE + 7) / 8, 256>>>(W4, b4, ii);
    k6_out<<<(NN + 1) / 2, 256>>>(x, W7, out);
}

// round 11
// speedup vs baseline: 1.3658x; 1.3658x over previous
#include <cuda_runtime.h>
#include <cuda_fp16.h>
#include <math.h>

#define NN 10000
#define NE 200000
#define NT 400000
#define NORB 9
#define HD 128
#define CFD 64
#define CD 32
#define R_TOT (NE * NORB)   // 1,800,000 flattened (edge,orb) rows

typedef unsigned long long u64;
typedef unsigned int u32;

// ---------------- scratch (device globals; no allocation allowed) ----------
__device__ float g_h[NN * 64];                     // [0:32)=silu(xh), [32:64)=sigm(xk)
__device__ __half g_cji_c[(size_t)NE * NORB * CD]; // 115.2 MB (fp16)
__device__ __half g_ckj_n[(size_t)NE * NORB * CD]; // 115.2 MB (fp16, pre-normalized)
__device__ float g_rbw[NE * NORB];
__device__ float g_agg[(size_t)NE * CD];
__device__ float g_nf[(size_t)NE * CD];            // node-feature MLP output
__device__ float g_acc[NN * CD];

// ---- activations (proven __expf path; tanh.approx regressed on sm_103a) -----
__device__ __forceinline__ float sigm(float x) { return 1.f / (1.f + __expf(-x)); }
__device__ __forceinline__ float silu(float x) { return x * sigm(x); }

__device__ __forceinline__ float warp_sum(float s) {
#pragma unroll
    for (int off = 16; off; off >>= 1) s += __shfl_xor_sync(0xffffffffu, s, off);
    return s;
}

// ---- packed fp32x2 FFMA2 (k5b W4 gemm) -------------------------------------
__device__ __forceinline__ void fma2(u64& d, u64 a, u64 b) {
    asm("fma.rn.f32x2 %0,%1,%2,%0;" : "+l"(d) : "l"(a), "l"(b));
}
__device__ __forceinline__ float unp_sum(u64 v) {
    float x, y; asm("mov.b64 {%0,%1},%2;" : "=f"(x), "=f"(y) : "l"(v)); return x + y;
}

// ---- tf32 helpers -----------------------------------------------------------
__device__ __forceinline__ u32 to_tf32(float f) {
    u32 r; asm("cvt.rna.tf32.f32 %0,%1;" : "=r"(r) : "f"(f)); return r;
}
__device__ __forceinline__ void mma_tf32(float& c0, float& c1, float& c2, float& c3,
                                         u32 a0, u32 a1, u32 a2, u32 a3,
                                         u32 b0, u32 b1) {
    asm("mma.sync.aligned.m16n8k8.row.col.f32.tf32.tf32.f32 "
        "{%0,%1,%2,%3},{%4,%5,%6,%7},{%8,%9},{%0,%1,%2,%3};"
        : "+f"(c0), "+f"(c1), "+f"(c2), "+f"(c3)
        : "r"(a0), "r"(a1), "r"(a2), "r"(a3), "r"(b0), "r"(b1));
}

// ---------------- K0: zero accumulators + rb_w = rb * cutoff_w -------------
__global__ void k0_init(const float* __restrict__ rb, const float* __restrict__ cw) {
    int i = blockIdx.x * blockDim.x + threadIdx.x;
    if (i < NE * CD) g_agg[i] = 0.f;
    if (i < NN * CD) g_acc[i] = 0.f;
    if (i < NE * NORB) g_rbw[i] = rb[i] * cw[i / NORB];
}

// ---------------- K1: h = x @ W1^T + b1; store silu(xh) / sigm(xk) ----------
__global__ void __launch_bounds__(256) k1_node(const float* __restrict__ x,
                                               const float* __restrict__ W1,
                                               const float* __restrict__ b1) {
    __shared__ float sW[HD * 64];
    __shared__ float sx[4][HD];
    int tid = threadIdx.x;
    for (int idx = tid; idx < 64 * HD; idx += 256) {
        int o = idx / HD, k = idx % HD;
        sW[k * 64 + o] = W1[idx];
    }
    int n0 = blockIdx.x * 4;
#pragma unroll
    for (int r = 0; r < 4; r++) {
        int n = n0 + r;
        if (n < NN)
            for (int k = tid; k < HD; k += 256) sx[r][k] = x[n * HD + k];
    }
    __syncthreads();
    int r = tid / 64, o = tid % 64;
    int n = n0 + r;
    if (n >= NN) return;
    float acc = b1[o];
#pragma unroll 8
    for (int k = 0; k < HD; k++) acc = fmaf(sx[r][k], sW[k * 64 + o], acc);
    g_h[n * 64 + o] = (o < 32) ? silu(acc) : sigm(acc);
}

// ---------------- K2: edge coeff MLP, tf32 tensor cores, A2 aliased on A1 ----
__global__ void __launch_bounds__(256) k2_mma(const float* __restrict__ cji,
                                              const float* __restrict__ W2,
                                              const float* __restrict__ W3) {
    __shared__ u32 sW2[32 * 68];       // [n][k] pad 68 (tf32 bits)
    __shared__ u32 sW3[64 * 36];       // [n][k] pad 36
    __shared__ u32 sA1[8][16 * 68];    // per-warp tile; A2 overlays same buffer
    int tid = threadIdx.x;
    for (int idx = tid; idx < 32 * 64; idx += 256) {
        int n = idx >> 6, k = idx & 63;
        sW2[n * 68 + k] = to_tf32(W2[idx]);
    }
    for (int idx = tid; idx < 64 * 32; idx += 256) {
        int n = idx >> 5, k = idx & 31;
        sW3[n * 36 + k] = to_tf32(W3[idx]);
    }
    __syncthreads();

    int w = tid >> 5, lane = tid & 31;
    int gq = lane >> 2, tq = lane & 3;
    long row0 = (long)blockIdx.x * 128 + w * 16;
    u32* A1 = sA1[w];
    u32* A2 = sA1[w];   // alias: A1 fully consumed into regs before A2 writes

    for (int i = lane; i < 256; i += 32) {
        int rl = i >> 4, c4 = i & 15;
        long rg = row0 + rl;
        uint4 v = make_uint4(0u, 0u, 0u, 0u);
        if (rg < R_TOT) {
            float4 f = *(const float4*)(cji + rg * 64 + c4 * 4);
            v.x = to_tf32(silu(f.x)); v.y = to_tf32(silu(f.y));
            v.z = to_tf32(silu(f.z)); v.w = to_tf32(silu(f.w));
        }
        *(uint4*)&A1[rl * 68 + c4 * 4] = v;
    }
    __syncwarp();

    float c1[4][4];
#pragma unroll
    for (int nt = 0; nt < 4; nt++)
#pragma unroll
        for (int j = 0; j < 4; j++) c1[nt][j] = 0.f;
#pragma unroll
    for (int k0 = 0; k0 < 64; k0 += 8) {
        u32 a0 = A1[gq * 68 + k0 + tq];
        u32 a1 = A1[(gq + 8) * 68 + k0 + tq];
        u32 a2 = A1[gq * 68 + k0 + tq + 4];
        u32 a3 = A1[(gq + 8) * 68 + k0 + tq + 4];
#pragma unroll
        for (int nt = 0; nt < 4; nt++) {
            u32 b0 = sW2[(nt * 8 + gq) * 68 + k0 + tq];
            u32 b1 = sW2[(nt * 8 + gq) * 68 + k0 + tq + 4];
            mma_tf32(c1[nt][0], c1[nt][1], c1[nt][2], c1[nt][3], a0, a1, a2, a3, b0, b1);
        }
    }
    __syncwarp();
#pragma unroll
    for (int nt = 0; nt < 4; nt++) {
        A2[gq * 36 + nt * 8 + 2 * tq]           = to_tf32(silu(c1[nt][0]));
        A2[gq * 36 + nt * 8 + 2 * tq + 1]       = to_tf32(silu(c1[nt][1]));
        A2[(gq + 8) * 36 + nt * 8 + 2 * tq]     = to_tf32(silu(c1[nt][2]));
        A2[(gq + 8) * 36 + nt * 8 + 2 * tq + 1] = to_tf32(silu(c1[nt][3]));
    }
    __syncwarp();

    float c2[8][4];
#pragma unroll
    for (int nt = 0; nt < 8; nt++)
#pragma unroll
        for (int j = 0; j < 4; j++) c2[nt][j] = 0.f;
#pragma unroll
    for (int k0 = 0; k0 < 32; k0 += 8) {
        u32 a0 = A2[gq * 36 + k0 + tq];
        u32 a1 = A2[(gq + 8) * 36 + k0 + tq];
        u32 a2 = A2[gq * 36 + k0 + tq + 4];
        u32 a3 = A2[(gq + 8) * 36 + k0 + tq + 4];
#pragma unroll
        for (int nt = 0; nt < 8; nt++) {
            u32 b0 = sW3[(nt * 8 + gq) * 36 + k0 + tq];
            u32 b1 = sW3[(nt * 8 + gq) * 36 + k0 + tq + 4];
            mma_tf32(c2[nt][0], c2[nt][1], c2[nt][2], c2[nt][3], a0, a1, a2, a3, b0, b1);
        }
    }

    long rA = row0 + gq, rB = row0 + gq + 8;
    if (rA < R_TOT) {
#pragma unroll
        for (int nt = 0; nt < 4; nt++)
            *(__half2*)&g_cji_c[rA * 32 + nt * 8 + 2 * tq] = __floats2half2_rn(c2[nt][0], c2[nt][1]);
    }
    if (rB < R_TOT) {
#pragma unroll
        for (int nt = 0; nt < 4; nt++)
            *(__half2*)&g_cji_c[rB * 32 + nt * 8 + 2 * tq] = __floats2half2_rn(c2[nt][2], c2[nt][3]);
    }
    float sa = 0.f, sb = 0.f;
#pragma unroll
    for (int nt = 4; nt < 8; nt++) {
        sa = fmaf(c2[nt][0], c2[nt][0], fmaf(c2[nt][1], c2[nt][1], sa));
        sb = fmaf(c2[nt][2], c2[nt][2], fmaf(c2[nt][3], c2[nt][3], sb));
    }
    sa += __shfl_xor_sync(0xffffffffu, sa, 1);
    sa += __shfl_xor_sync(0xffffffffu, sa, 2);
    sb += __shfl_xor_sync(0xffffffffu, sb, 1);
    sb += __shfl_xor_sync(0xffffffffu, sb, 2);
    float ia = 1.f / fmaxf(sqrtf(sa), 1e-12f);
    float ib = 1.f / fmaxf(sqrtf(sb), 1e-12f);
    if (rA < R_TOT) {
#pragma unroll
        for (int nt = 4; nt < 8; nt++)
            *(__half2*)&g_ckj_n[rA * 32 + (nt - 4) * 8 + 2 * tq] =
                __floats2half2_rn(c2[nt][0] * ia, c2[nt][1] * ia);
    }
    if (rB < R_TOT) {
#pragma unroll
        for (int nt = 4; nt < 8; nt++)
            *(__half2*)&g_ckj_n[rB * 32 + (nt - 4) * 8 + 2 * tq] =
                __floats2half2_rn(c2[nt][2] * ib, c2[nt][3] * ib);
    }
}

// ---------------- K5a: nf MLP on tensor cores, A2 aliased on A1 --------------
__global__ void __launch_bounds__(256) k5a_nf(const float* __restrict__ W5,
                                              const float* __restrict__ b5,
                                              const float* __restrict__ W6,
                                              const float* __restrict__ b6,
                                              const int* __restrict__ idx_i,
                                              const int* __restrict__ idx_j) {
    __shared__ u32 sW5[32 * 68];
    __shared__ u32 sW6[32 * 36];
    __shared__ float sb5[32], sb6[32];
    __shared__ u32 sA1[8][16 * 68];   // A2 overlays
    int tid = threadIdx.x;
    for (int idx = tid; idx < 32 * 64; idx += 256) {
        int n = idx >> 6, k = idx & 63;
        sW5[n * 68 + k] = to_tf32(W5[idx]);
    }
    for (int idx = tid; idx < 32 * 32; idx += 256) {
        int n = idx >> 5, k = idx & 31;
        sW6[n * 36 + k] = to_tf32(W6[idx]);
    }
    if (tid < 32) { sb5[tid] = b5[tid]; sb6[tid] = b6[tid]; }
    __syncthreads();

    int w = tid >> 5, lane = tid & 31;
    int gq = lane >> 2, tq = lane & 3;
    long row0 = (long)blockIdx.x * 128 + w * 16;
    u32* A1 = sA1[w];
    u32* A2 = sA1[w];

    for (int i = lane; i < 256; i += 32) {
        int rl = i >> 4, c4 = i & 15;
        long e = row0 + rl;
        uint4 v = make_uint4(0u, 0u, 0u, 0u);
        if (e < NE) {
            int n = (c4 < 8) ? __ldg(&idx_i[e]) : __ldg(&idx_j[e]);
            float4 f = *(const float4*)&g_h[n * 64 + (c4 & 7) * 4];
            v.x = to_tf32(f.x); v.y = to_tf32(f.y);
            v.z = to_tf32(f.z); v.w = to_tf32(f.w);
        }
        *(uint4*)&A1[rl * 68 + c4 * 4] = v;
    }
    __syncwarp();

    float c1[4][4];
#pragma unroll
    for (int nt = 0; nt < 4; nt++)
#pragma unroll
        for (int j = 0; j < 4; j++) c1[nt][j] = 0.f;
#pragma unroll
    for (int k0 = 0; k0 < 64; k0 += 8) {
        u32 a0 = A1[gq * 68 + k0 + tq];
        u32 a1 = A1[(gq + 8) * 68 + k0 + tq];
        u32 a2 = A1[gq * 68 + k0 + tq + 4];
        u32 a3 = A1[(gq + 8) * 68 + k0 + tq + 4];
#pragma unroll
        for (int nt = 0; nt < 4; nt++) {
            u32 b0 = sW5[(nt * 8 + gq) * 68 + k0 + tq];
            u32 b1 = sW5[(nt * 8 + gq) * 68 + k0 + tq + 4];
            mma_tf32(c1[nt][0], c1[nt][1], c1[nt][2], c1[nt][3], a0, a1, a2, a3, b0, b1);
        }
    }
    __syncwarp();
#pragma unroll
    for (int nt = 0; nt < 4; nt++) {
        int col = nt * 8 + 2 * tq;
        A2[gq * 36 + col]           = to_tf32(silu(c1[nt][0] + sb5[col]));
        A2[gq * 36 + col + 1]       = to_tf32(silu(c1[nt][1] + sb5[col + 1]));
        A2[(gq + 8) * 36 + col]     = to_tf32(silu(c1[nt][2] + sb5[col]));
        A2[(gq + 8) * 36 + col + 1] = to_tf32(silu(c1[nt][3] + sb5[col + 1]));
    }
    __syncwarp();

    float c2[4][4];
#pragma unroll
    for (int nt = 0; nt < 4; nt++)
#pragma unroll
        for (int j = 0; j < 4; j++) c2[nt][j] = 0.f;
#pragma unroll
    for (int k0 = 0; k0 < 32; k0 += 8) {
        u32 a0 = A2[gq * 36 + k0 + tq];
        u32 a1 = A2[(gq + 8) * 36 + k0 + tq];
        u32 a2 = A2[gq * 36 + k0 + tq + 4];
        u32 a3 = A2[(gq + 8) * 36 + k0 + tq + 4];
#pragma unroll
        for (int nt = 0; nt < 4; nt++) {
            u32 b0 = sW6[(nt * 8 + gq) * 36 + k0 + tq];
            u32 b1 = sW6[(nt * 8 + gq) * 36 + k0 + tq + 4];
            mma_tf32(c2[nt][0], c2[nt][1], c2[nt][2], c2[nt][3], a0, a1, a2, a3, b0, b1);
        }
    }
    long rA = row0 + gq, rB = row0 + gq + 8;
    if (rA < NE) {
#pragma unroll
        for (int nt = 0; nt < 4; nt++) {
            int col = nt * 8 + 2 * tq;
            *(float2*)&g_nf[rA * 32 + col] =
                make_float2(c2[nt][0] + sb6[col], c2[nt][1] + sb6[col + 1]);
        }
    }
    if (rB < NE) {
#pragma unroll
        for (int nt = 0; nt < 4; nt++) {
            int col = nt * 8 + 2 * tq;
            *(float2*)&g_nf[rB * 32 + col] =
                make_float2(c2[nt][2] + sb6[col], c2[nt][3] + sb6[col + 1]);
        }
    }
}

// ---------------- K3: triplets -> edge aggregation, 2 triplets per warp ------
__global__ void __launch_bounds__(256) k3_tri(const float* __restrict__ shb,
                                              const int* __restrict__ e_kj,
                                              const int* __restrict__ e_ji,
                                              const int* __restrict__ t_k) {
    int w = threadIdx.x >> 5, lane = threadIdx.x & 31;
    int t0 = (blockIdx.x * 8 + w) * 2;
    if (t0 >= NT) return;
    int t1 = t0 + 1;
    int kj0 = e_kj[t0], ji0 = e_ji[t0], kn0 = t_k[t0];
    int kj1 = e_kj[t1], ji1 = e_ji[t1], kn1 = t_k[t1];
    float acc0 = 0.f, acc1 = 0.f;
#pragma unroll
    for (int d = 0; d < NORB; d++) {
        float cf0 = __ldg(&g_rbw[kj0 * NORB + d]) * __ldg(&shb[t0 * NORB + d]);
        float cf1 = __ldg(&g_rbw[kj1 * NORB + d]) * __ldg(&shb[t1 * NORB + d]);
        float ck0 = __half2float(__ldg(&g_ckj_n[((size_t)kj0 * NORB + d) * CD + lane]));
        float ck1 = __half2float(__ldg(&g_ckj_n[((size_t)kj1 * NORB + d) * CD + lane]));
        acc0 = fmaf(cf0, ck0, acc0);
        acc1 = fmaf(cf1, ck1, acc1);
    }
    float s0 = acc0 * acc0, s1 = acc1 * acc1;
#pragma unroll
    for (int off = 16; off; off >>= 1) {
        s0 += __shfl_xor_sync(0xffffffffu, s0, off);
        s1 += __shfl_xor_sync(0xffffffffu, s1, off);
    }
    float tw0 = acc0 * (1.f / fmaxf(sqrtf(s0), 1e-12f)) * g_h[kn0 * 64 + 32 + lane];
    float tw1 = acc1 * (1.f / fmaxf(sqrtf(s1), 1e-12f)) * g_h[kn1 * 64 + 32 + lane];
    atomicAdd(&g_agg[(size_t)ji0 * CD + lane], tw0);
    atomicAdd(&g_agg[(size_t)ji1 * CD + lane], tw1);
}

// ---------------- K5b: tbw + lcao (batched butterflies) + scatter ------------
__global__ void __launch_bounds__(256) k5b_edge(const float* __restrict__ W4,
                                                const float* __restrict__ b4,
                                                const int* __restrict__ idx_i) {
    __shared__ __align__(16) float sW4[32 * 36];
    __shared__ __align__(16) float sag[8][32];
    int tid = threadIdx.x;
    for (int idx = tid; idx < 32 * 32; idx += 256) {
        int c = idx / 32, k = idx % 32;
        sW4[c * 36 + k] = W4[idx];
    }
    __syncthreads();
    int w = tid >> 5, lane = tid & 31;
    int e = blockIdx.x * 8 + w;
    if (e >= NE) return;

    // hoist independent gathers to overlap with the agg-dependent GEMM below
    float vv[NORB];
    size_t base = (size_t)e * (NORB * CD);
#pragma unroll
    for (int d = 0; d < NORB; d++)
        vv[d] = __half2float(__ldg(&g_cji_c[base + d * 32 + lane]));
    float nf = __ldg(&g_nf[(size_t)e * CD + lane]);
    float rw[NORB];
#pragma unroll
    for (int d = 0; d < NORB; d++) rw[d] = __ldg(&g_rbw[e * NORB + d]);

    // tbw = silu(agg) @ W4^T + b4
    sag[w][lane] = silu(g_agg[(size_t)e * CD + lane]);
    __syncwarp();
    u64 t2 = 0ull;
#pragma unroll
    for (int k4 = 0; k4 < 8; k4++) {
        ulonglong2 wv = *(const ulonglong2*)&sW4[lane * 36 + k4 * 4];
        ulonglong2 av = *(const ulonglong2*)&sag[w][k4 * 4];
        fma2(t2, av.x, wv.x);
        fma2(t2, av.y, wv.y);
    }
    float tb = 1.f + b4[lane] + unp_sum(t2);

    // lcao: lc[c] = tb[c] * sum_d (rbw[d]/||cji_c[d,:]*tb||) * cji_c[d][c]
    float ss[NORB];
#pragma unroll
    for (int d = 0; d < NORB; d++) {
        float t = vv[d] * tb;
        ss[d] = t * t;
    }
#pragma unroll
    for (int off = 16; off; off >>= 1) {
#pragma unroll
        for (int d = 0; d < NORB; d++)
            ss[d] += __shfl_xor_sync(0xffffffffu, ss[d], off);
    }
    float lc = 0.f;
#pragma unroll
    for (int d = 0; d < NORB; d++) {
        float inv = 1.f / fmaxf(sqrtf(ss[d]), 1e-12f);
        lc = fmaf(rw[d] * inv, vv[d], lc);
    }
    lc *= tb;
    float s = warp_sum(lc * lc);
    lc *= 1.f / fmaxf(sqrtf(s), 1e-12f);

    int ni = idx_i[e];
    atomicAdd(&g_acc[ni * CD + lane], lc * nf);
}

// ---------------- K6: out = x + acc @ W7^T ----------------------------------
__global__ void __launch_bounds__(256) k6_out(const float* __restrict__ x,
                                              const float* __restrict__ W7,
                                              float* __restrict__ out) {
    __shared__ float sW[32 * 128];
    __shared__ float sa[2][32];
    int tid = threadIdx.x;
    for (int idx = tid; idx < 128 * 32; idx += 256) {
        int hc = idx / 32, c = idx % 32;
        sW[c * 128 + hc] = W7[idx];
    }
    int n0 = blockIdx.x * 2;
    if (tid < 64) {
        int r = tid >> 5, c = tid & 31;
        int n = n0 + r;
        if (n < NN) sa[r][c] = g_acc[n * 32 + c];
    }
    __syncthreads();
    int r = tid >> 7, hc = tid & 127;
    int n = n0 + r;
    if (n >= NN) return;
    float acc = x[n * 128 + hc];
#pragma unroll
    for (int c = 0; c < 32; c++) acc = fmaf(sa[r][c], sW[c * 128 + hc], acc);
    out[n * 128 + hc] = acc;
}

// ---------------- host launcher ---------------------------------------------
extern "C" void kernel_launch(void* const* d_in, const int* in_sizes, int n_in,
                              void* d_out, int out_size) {
    int o_ii, o_ij, o_tk, o_ekj, o_eji;
    int o_W1, o_b1, o_W2, o_W3, o_W4, o_b4, o_W5, o_b5, o_W6, o_b6, o_W7;
    if (in_sizes[5] == NE) { // dict order: idx_i at slot 5
        o_ii = 5; o_ij = 6; o_tk = 7; o_ekj = 8; o_eji = 9;
        o_W1 = 10; o_b1 = 11; o_W2 = 12; o_W3 = 13; o_W4 = 14; o_b4 = 15;
        o_W5 = 16; o_b5 = 17; o_W6 = 18; o_b6 = 19; o_W7 = 20;
    } else {                 // signature order: W1 at slot 5
        o_W1 = 5; o_b1 = 6; o_W2 = 7; o_W3 = 8; o_W4 = 9; o_b4 = 10;
        o_W5 = 11; o_b5 = 12; o_W6 = 13; o_b6 = 14; o_W7 = 15;
        o_ii = 16; o_ij = 17; o_tk = 18; o_ekj = 19; o_eji = 20;
    }
    const float* x   = (const float*)d_in[0];
    const float* cji = (const float*)d_in[1];
    const float* cw  = (const float*)d_in[2];
    const float* rb  = (const float*)d_in[3];
    const float* shb = (const float*)d_in[4];
    const int* ii  = (const int*)d_in[o_ii];
    const int* ij  = (const int*)d_in[o_ij];
    const int* tk  = (const int*)d_in[o_tk];
    const int* ekj = (const int*)d_in[o_ekj];
    const int* eji = (const int*)d_in[o_eji];
    const float* W1 = (const float*)d_in[o_W1];
    const float* b1 = (const float*)d_in[o_b1];
    const float* W2 = (const float*)d_in[o_W2];
    const float* W3 = (const float*)d_in[o_W3];
    const float* W4 = (const float*)d_in[o_W4];
    const float* b4 = (const float*)d_in[o_b4];
    const float* W5 = (const float*)d_in[o_W5];
    const float* b5 = (const float*)d_in[o_b5];
    const float* W6 = (const float*)d_in[o_W6];
    const float* b6 = (const float*)d_in[o_b6];
    const float* W7 = (const float*)d_in[o_W7];
    float* out = (float*)d_out;

    k0_init<<<(NE * CD + 255) / 256, 256>>>(rb, cw);
    k1_node<<<(NN + 3) / 4, 256>>>(x, W1, b1);
    k2_mma<<<(R_TOT + 127) / 128, 256>>>(cji, W2, W3);
    k5a_nf<<<(NE + 127) / 128, 256>>>(W5, b5, W6, b6, ii, ij);
    k3_tri<<<(NT + 15) / 16, 256>>>(shb, ekj, eji, tk);
    k5b_edge<<<(NE + 7) / 8, 256>>>(W4, b4, ii);
    k6_out<<<(NN + 1) / 2, 256>>>(x, W7, out);
}